// round 1
// baseline (speedup 1.0000x reference)
#include <cuda_runtime.h>
#include <cstdint>
#include <cstddef>

#define BB 2
#define SS 2048
#define EE 1024
#define HH 16
#define DHD 64
#define HID 256

// ---------------- scratch (device globals: allocation-free) ----------------
__device__ float g_Q[(size_t)BB * SS * EE];
__device__ float g_K[(size_t)BB * SS * EE];
__device__ float g_V[(size_t)BB * SS * EE];
__device__ float g_CTX[(size_t)BB * SS * EE];
__device__ float g_P[(size_t)BB * HH * SS * SS];   // 537 MB scores/probs
__device__ float g_gate[BB * HH];

// ---------------- helpers ----------------
__device__ __forceinline__ float fast_exp(float x) {
    // x <= 0 here. exp(x) = 2^(x*log2e); poly on reduced range, FFMA-only.
    float y = x * 1.4426950408889634f;
    float n = rintf(y);
    float t = (y - n) * 0.6931471805599453f;            // t in [-0.3466, 0.3466]
    float p = 1.0f + t * (1.0f + t * (0.5f + t * (0.16666667f +
              t * (0.041666668f + t * 0.008333334f))));
    n = fmaxf(n, -126.0f);
    return p * __int_as_float(((int)n + 127) << 23);
}

// ---------------- sync gate: sigmoid(relu(sf@Ws1+bs1)@Ws2+bs2) * 1/sqrt(DH) --
__global__ void gate_kernel(const float* __restrict__ sf,
                            const float* __restrict__ Ws1, const float* __restrict__ bs1,
                            const float* __restrict__ Ws2, const float* __restrict__ bs2)
{
    __shared__ float h1[BB][HID];
    int t = threadIdx.x;                      // 256 threads = HID
    for (int b = 0; b < BB; ++b) {
        float acc = bs1[t];
        for (int e = 0; e < EE; ++e)
            acc += sf[b * EE + e] * Ws1[(size_t)e * HID + t];
        h1[b][t] = fmaxf(acc, 0.0f);
    }
    __syncthreads();
    if (t < BB * HH) {
        int b = t / HH, h = t % HH;
        float acc = bs2[h];
        for (int k = 0; k < HID; ++k)
            acc += h1[b][k] * Ws2[k * HH + h];
        float sig = 1.0f / (1.0f + __expf(-acc));
        g_gate[b * HH + h] = sig * 0.125f;    // includes 1/sqrt(64)
    }
}

// ---------------- NN GEMM 128x128x8, C = A@W (+bias), lda = K ----------------
__global__ __launch_bounds__(256, 2)
void gemm_nn128(const float* __restrict__ A, const float* __restrict__ W,
                const float* __restrict__ bias, float* __restrict__ C,
                int K, int ldb, int ldc)
{
    __shared__ float As[8][132];
    __shared__ float Bs[8][132];
    const int tid = threadIdx.x;
    const int tx = tid & 15, ty = tid >> 4;
    const int br = blockIdx.y, bc = blockIdx.x;

    const int arow = tid >> 1, ac4 = (tid & 1) * 4;
    const int brow = tid >> 5, bcol = (tid & 31) * 4;

    const float* Ag = A + (size_t)(br * 128 + arow) * K + ac4;
    const float* Bg = W + (size_t)brow * ldb + bc * 128 + bcol;

    float4 an = *(const float4*)Ag;
    float4 bn = *(const float4*)Bg;

    float acc[8][8];
#pragma unroll
    for (int i = 0; i < 8; ++i)
#pragma unroll
        for (int j = 0; j < 8; ++j) acc[i][j] = 0.0f;

    const int nk = K >> 3;
    for (int kt = 0; kt < nk; ++kt) {
        As[ac4 + 0][arow] = an.x; As[ac4 + 1][arow] = an.y;
        As[ac4 + 2][arow] = an.z; As[ac4 + 3][arow] = an.w;
        *(float4*)&Bs[brow][bcol] = bn;
        __syncthreads();
        if (kt + 1 < nk) {
            an = *(const float4*)(Ag + (kt + 1) * 8);
            bn = *(const float4*)(Bg + (size_t)(kt + 1) * 8 * ldb);
        }
#pragma unroll
        for (int k = 0; k < 8; ++k) {
            float4 a0 = *(const float4*)&As[k][ty * 4];
            float4 a1 = *(const float4*)&As[k][64 + ty * 4];
            float4 b0 = *(const float4*)&Bs[k][tx * 4];
            float4 b1 = *(const float4*)&Bs[k][64 + tx * 4];
            float a[8] = {a0.x, a0.y, a0.z, a0.w, a1.x, a1.y, a1.z, a1.w};
            float bb[8] = {b0.x, b0.y, b0.z, b0.w, b1.x, b1.y, b1.z, b1.w};
#pragma unroll
            for (int i = 0; i < 8; ++i)
#pragma unroll
                for (int j = 0; j < 8; ++j)
                    acc[i][j] += a[i] * bb[j];
        }
        __syncthreads();
    }

    const int c0 = bc * 128 + tx * 4;
    float4 bias0 = make_float4(0, 0, 0, 0), bias1 = make_float4(0, 0, 0, 0);
    if (bias) { bias0 = *(const float4*)&bias[c0]; bias1 = *(const float4*)&bias[c0 + 64]; }
#pragma unroll
    for (int i = 0; i < 8; ++i) {
        int row = br * 128 + ((i < 4) ? ty * 4 + i : 64 + ty * 4 + (i - 4));
        float* Cp = C + (size_t)row * ldc + c0;
        float4 v0 = make_float4(acc[i][0] + bias0.x, acc[i][1] + bias0.y,
                                acc[i][2] + bias0.z, acc[i][3] + bias0.w);
        float4 v1 = make_float4(acc[i][4] + bias1.x, acc[i][5] + bias1.y,
                                acc[i][6] + bias1.z, acc[i][7] + bias1.w);
        *(float4*)Cp = v0;
        *(float4*)(Cp + 64) = v1;
    }
}

// ---------------- scores: S[b,h,i,j] = gate * sum_d Q[b,i,h,d]*K[b,j,h,d] ----
__global__ __launch_bounds__(256, 2)
void scores_nt(const float* __restrict__ Q, const float* __restrict__ Kt,
               float* __restrict__ P)
{
    extern __shared__ float sm[];
    float* As = sm;                 // [128][68], rows = queries, cols = d
    float* Bs = sm + 128 * 68;      // [128][68], rows = keys

    const int tid = threadIdx.x;
    const int bh = blockIdx.z, b = bh >> 4, h = bh & 15;
    const int mi = blockIdx.y * 128, nj = blockIdx.x * 128;

    const float* Ag = Q + (size_t)b * SS * EE + h * 64;
    const float* Bg = Kt + (size_t)b * SS * EE + h * 64;

#pragma unroll
    for (int it = 0; it < 8; ++it) {
        int idx = it * 1024 + tid * 4;
        int r = idx >> 6, k = idx & 63;
        *(float4*)&As[r * 68 + k] = *(const float4*)&Ag[(size_t)(mi + r) * EE + k];
        *(float4*)&Bs[r * 68 + k] = *(const float4*)&Bg[(size_t)(nj + r) * EE + k];
    }
    __syncthreads();

    const int tx = tid & 15, ty = tid >> 4;
    float acc[8][8];
#pragma unroll
    for (int i = 0; i < 8; ++i)
#pragma unroll
        for (int j = 0; j < 8; ++j) acc[i][j] = 0.0f;

#pragma unroll
    for (int k4 = 0; k4 < 16; ++k4) {
        float4 a[8];
#pragma unroll
        for (int i = 0; i < 8; ++i)
            a[i] = *(const float4*)&As[(ty * 8 + i) * 68 + k4 * 4];
#pragma unroll
        for (int j = 0; j < 8; ++j) {
            float4 bv = *(const float4*)&Bs[(tx + 16 * j) * 68 + k4 * 4];
#pragma unroll
            for (int i = 0; i < 8; ++i)
                acc[i][j] += a[i].x * bv.x + a[i].y * bv.y + a[i].z * bv.z + a[i].w * bv.w;
        }
    }

    const float g = g_gate[bh];
    float* Crow = P + ((size_t)bh * SS + mi) * SS + nj;
#pragma unroll
    for (int i = 0; i < 8; ++i) {
        float* cp = Crow + (size_t)(ty * 8 + i) * SS;
#pragma unroll
        for (int j = 0; j < 8; ++j)
            cp[tx + 16 * j] = acc[i][j] * g;
    }
}

// ---------------- softmax over j for all 16 heads + head-mean ---------------
__global__ __launch_bounds__(256)
void softmax_mean(float* __restrict__ Pm, float* __restrict__ om)
{
    __shared__ float meanbuf[SS];
    __shared__ float red[8];
    const int i = blockIdx.x, b = blockIdx.y;
    const int tid = threadIdx.x;
    const int lane = tid & 31, wid = tid >> 5;

#pragma unroll
    for (int r = 0; r < 8; ++r) meanbuf[tid + 256 * r] = 0.0f;

    for (int h = 0; h < HH; ++h) {
        float* row = Pm + ((size_t)(b * HH + h) * SS + i) * SS;
        float s[8];
        float mx = -3.4e38f;
#pragma unroll
        for (int r = 0; r < 8; ++r) { s[r] = row[tid + 256 * r]; mx = fmaxf(mx, s[r]); }
#pragma unroll
        for (int o = 16; o > 0; o >>= 1) mx = fmaxf(mx, __shfl_xor_sync(0xffffffffu, mx, o));
        if (lane == 0) red[wid] = mx;
        __syncthreads();
        float m2 = red[0];
#pragma unroll
        for (int w = 1; w < 8; ++w) m2 = fmaxf(m2, red[w]);
        __syncthreads();

        float sum = 0.0f;
#pragma unroll
        for (int r = 0; r < 8; ++r) { s[r] = fast_exp(s[r] - m2); sum += s[r]; }
#pragma unroll
        for (int o = 16; o > 0; o >>= 1) sum += __shfl_xor_sync(0xffffffffu, sum, o);
        if (lane == 0) red[wid] = sum;
        __syncthreads();
        float tot = 0.0f;
#pragma unroll
        for (int w = 0; w < 8; ++w) tot += red[w];
        float inv = 1.0f / tot;
#pragma unroll
        for (int r = 0; r < 8; ++r) {
            float p = s[r] * inv;
            row[tid + 256 * r] = p;
            meanbuf[tid + 256 * r] += p * 0.0625f;
        }
        __syncthreads();
    }
    float* o = om + (size_t)(b * SS + i) * SS;
#pragma unroll
    for (int r = 0; r < 8; ++r) o[tid + 256 * r] = meanbuf[tid + 256 * r];
}

// ---------------- PV: ctx[b,i,h,:] = sum_j P[b,h,i,j] * V[b,j,h,:] -----------
__global__ __launch_bounds__(256, 2)
void pv_gemm(const float* __restrict__ P, const float* __restrict__ V,
             float* __restrict__ C)
{
    __shared__ float As[8][132];
    __shared__ float Bs[8][68];
    const int tid = threadIdx.x;
    const int tx = tid & 15, ty = tid >> 4;
    const int br = blockIdx.y;
    const int bh = blockIdx.z, b = bh >> 4, h = bh & 15;

    const float* A = P + (size_t)bh * SS * SS;
    const float* Bv = V + (size_t)b * SS * EE + h * 64;
    float* Cc = C + (size_t)b * SS * EE + h * 64;

    const int arow = tid >> 1, ac4 = (tid & 1) * 4;
    const float* Ag = A + (size_t)(br * 128 + arow) * SS + ac4;
    const int brow = tid >> 4, bcol = (tid & 15) * 4;   // active for tid<128
    const float* Bg = Bv + (size_t)brow * EE + bcol;

    float4 an = *(const float4*)Ag;
    float4 bn = (tid < 128) ? *(const float4*)Bg : make_float4(0, 0, 0, 0);

    float acc[8][4];
#pragma unroll
    for (int i = 0; i < 8; ++i)
#pragma unroll
        for (int j = 0; j < 4; ++j) acc[i][j] = 0.0f;

    const int nk = SS >> 3;   // 256
    for (int kt = 0; kt < nk; ++kt) {
        As[ac4 + 0][arow] = an.x; As[ac4 + 1][arow] = an.y;
        As[ac4 + 2][arow] = an.z; As[ac4 + 3][arow] = an.w;
        if (tid < 128) *(float4*)&Bs[brow][bcol] = bn;
        __syncthreads();
        if (kt + 1 < nk) {
            an = *(const float4*)(Ag + (kt + 1) * 8);
            if (tid < 128) bn = *(const float4*)(Bg + (size_t)(kt + 1) * 8 * EE);
        }
#pragma unroll
        for (int k = 0; k < 8; ++k) {
            float4 a0 = *(const float4*)&As[k][ty * 4];
            float4 a1 = *(const float4*)&As[k][64 + ty * 4];
            float4 b0 = *(const float4*)&Bs[k][tx * 4];
            float a[8] = {a0.x, a0.y, a0.z, a0.w, a1.x, a1.y, a1.z, a1.w};
            float bb[4] = {b0.x, b0.y, b0.z, b0.w};
#pragma unroll
            for (int i = 0; i < 8; ++i)
#pragma unroll
                for (int j = 0; j < 4; ++j)
                    acc[i][j] += a[i] * bb[j];
        }
        __syncthreads();
    }

#pragma unroll
    for (int i = 0; i < 8; ++i) {
        int row = br * 128 + ((i < 4) ? ty * 4 + i : 64 + ty * 4 + (i - 4));
        float4 v = make_float4(acc[i][0], acc[i][1], acc[i][2], acc[i][3]);
        *(float4*)&Cc[(size_t)row * EE + tx * 4] = v;
    }
}

// ---------------- launch ----------------
extern "C" void kernel_launch(void* const* d_in, const int* in_sizes, int n_in,
                              void* d_out, int out_size)
{
    const float* x   = (const float*)d_in[0];
    const float* sf  = (const float*)d_in[1];
    const float* Wq  = (const float*)d_in[2];
    const float* bq  = (const float*)d_in[3];
    const float* Wk  = (const float*)d_in[4];
    const float* bk  = (const float*)d_in[5];
    const float* Wv  = (const float*)d_in[6];
    const float* bv  = (const float*)d_in[7];
    const float* Ws1 = (const float*)d_in[8];
    const float* bs1 = (const float*)d_in[9];
    const float* Ws2 = (const float*)d_in[10];
    const float* bs2 = (const float*)d_in[11];
    const float* Wo  = (const float*)d_in[12];
    const float* bo  = (const float*)d_in[13];
    float* out = (float*)d_out;

    float *pQ, *pK, *pV, *pC, *pP;
    cudaGetSymbolAddress((void**)&pQ, g_Q);
    cudaGetSymbolAddress((void**)&pK, g_K);
    cudaGetSymbolAddress((void**)&pV, g_V);
    cudaGetSymbolAddress((void**)&pC, g_CTX);
    cudaGetSymbolAddress((void**)&pP, g_P);

    // 1. sync gate (tiny)
    gate_kernel<<<1, 256>>>(sf, Ws1, bs1, Ws2, bs2);

    // 2. QKV projections: [4096,1024] x [1024,1024] each
    dim3 gqkv(EE / 128, (BB * SS) / 128, 1);
    gemm_nn128<<<gqkv, 256>>>(x, Wq, bq, pQ, EE, EE, EE);
    gemm_nn128<<<gqkv, 256>>>(x, Wk, bk, pK, EE, EE, EE);
    gemm_nn128<<<gqkv, 256>>>(x, Wv, bv, pV, EE, EE, EE);

    // 3. scores = gate/sqrt(DH) * Q Kt  (per b,h)
    cudaFuncSetAttribute(scores_nt, cudaFuncAttributeMaxDynamicSharedMemorySize, 2 * 128 * 68 * 4);
    scores_nt<<<dim3(SS / 128, SS / 128, BB * HH), 256, 2 * 128 * 68 * 4>>>(pQ, pK, pP);

    // 4. softmax (in-place) + head-mean -> second half of d_out
    softmax_mean<<<dim3(SS, BB), 256>>>(pP, out + (size_t)BB * SS * EE);

    // 5. ctx = P @ V (per b,h)
    pv_gemm<<<dim3(1, SS / 128, BB * HH), 256>>>(pP, pV, pC);

    // 6. out = ctx @ Wo + bo -> first half of d_out
    gemm_nn128<<<dim3(EE / 128, (BB * SS) / 128, 1), 256>>>(pC, Wo, bo, out, EE, EE, EE);

    (void)in_sizes; (void)n_in; (void)out_size;
}

// round 2
// speedup vs baseline: 1.9463x; 1.9463x over previous
#include <cuda_runtime.h>
#include <cstdint>
#include <cstddef>

#define BB 2
#define SS 2048
#define EE 1024
#define HH 16
#define DHD 64
#define HID 256

// ---------------- scratch (device globals: allocation-free) ----------------
__device__ float g_Q[(size_t)BB * SS * EE];
__device__ float g_K[(size_t)BB * SS * EE];
__device__ float g_V[(size_t)BB * SS * EE];
__device__ float g_CTX[(size_t)BB * SS * EE];
__device__ float g_P[(size_t)BB * HH * SS * SS];   // 537 MB scores/probs
__device__ float g_gate[BB * HH];

// ---------------- helpers ----------------
__device__ __forceinline__ float fast_exp(float x) {
    float y = x * 1.4426950408889634f;
    float n = rintf(y);
    float t = (y - n) * 0.6931471805599453f;
    float p = 1.0f + t * (1.0f + t * (0.5f + t * (0.16666667f +
              t * (0.041666668f + t * 0.008333334f))));
    n = fmaxf(n, -126.0f);
    return p * __int_as_float(((int)n + 127) << 23);
}

__device__ __forceinline__ uint32_t f2tf32(float x) {
    uint32_t r; asm("cvt.rna.tf32.f32 %0, %1;" : "=r"(r) : "f"(x)); return r;
}

__device__ __forceinline__ void mma_tf32(float* d, const uint32_t* a, const uint32_t* b) {
    asm volatile("mma.sync.aligned.m16n8k8.row.col.f32.tf32.tf32.f32 "
                 "{%0,%1,%2,%3}, {%4,%5,%6,%7}, {%8,%9}, {%0,%1,%2,%3};"
                 : "+f"(d[0]), "+f"(d[1]), "+f"(d[2]), "+f"(d[3])
                 : "r"(a[0]), "r"(a[1]), "r"(a[2]), "r"(a[3]),
                   "r"(b[0]), "r"(b[1]));
}

// ---------------- sync gate ----------------
__global__ void gate_kernel(const float* __restrict__ sf,
                            const float* __restrict__ Ws1, const float* __restrict__ bs1,
                            const float* __restrict__ Ws2, const float* __restrict__ bs2)
{
    __shared__ float h1[BB][HID];
    int t = threadIdx.x;
    for (int b = 0; b < BB; ++b) {
        float acc = bs1[t];
        for (int e = 0; e < EE; ++e)
            acc += sf[b * EE + e] * Ws1[(size_t)e * HID + t];
        h1[b][t] = fmaxf(acc, 0.0f);
    }
    __syncthreads();
    if (t < BB * HH) {
        int b = t / HH, h = t % HH;
        float acc = bs2[h];
        for (int k = 0; k < HID; ++k)
            acc += h1[b][k] * Ws2[k * HH + h];
        float sig = 1.0f / (1.0f + __expf(-acc));
        g_gate[b * HH + h] = sig * 0.125f;
    }
}

// ======================= generic NN tf32 GEMM =======================
// C[M,N] = A[M,K] @ B[K,N] (+bias). BM=128, BK=16. Warp grid WR x WC.
// Per-z offsets: z = blockIdx.z, zb = z>>4, zh = z&15.
template<int BN, int WR, int WC>
__global__ __launch_bounds__(256)
void gemm_nn_tf32(const float* __restrict__ A, const float* __restrict__ B,
                  const float* __restrict__ bias, float* __restrict__ C,
                  int K, int lda, int ldb, int ldc,
                  size_t sAb, size_t sAh, size_t sBb, size_t sBh,
                  size_t sCb, size_t sCh)
{
    constexpr int WM = 128 / WR;        // warp tile rows
    constexpr int WN = BN / WC;         // warp tile cols
    constexpr int MF = WM / 16;         // m-frags
    constexpr int NF = WN / 8;          // n-frags
    constexpr int AST = 20;             // A smem stride (uint32)
    constexpr int BST = BN + 8;         // B smem stride
    constexpr int BLD = BN / 64;        // float4 B loads per thread (2 or 1)

    __shared__ uint32_t As[2][128 * AST];
    __shared__ uint32_t Bs[2][16 * BST];

    const int tid = threadIdx.x;
    const int lane = tid & 31, warp = tid >> 5;
    const int wr = warp % WR, wc = warp / WR;
    const int lr = lane >> 2, lc = lane & 3;

    const int z = blockIdx.z, zb = z >> 4, zh = z & 15;
    A += zb * sAb + zh * sAh;
    B += zb * sBb + zh * sBh;
    C += zb * sCb + zh * sCh;

    const int bm = blockIdx.y * 128;
    const int bn = blockIdx.x * BN;

    // A load indices: 2 float4 per thread
    const int ar = tid >> 2, ac = (tid & 3) * 4;
    // B load indices
    const int brw = (BLD == 2) ? (tid >> 5) : (tid >> 4);
    const int bcl = (BLD == 2) ? ((tid & 31) * 4) : ((tid & 15) * 4);

    float4 av[2], bv[BLD];

    auto load_regs = [&](int kt) {
        int k0 = kt * 16;
        av[0] = *(const float4*)&A[(size_t)(bm + ar) * lda + k0 + ac];
        av[1] = *(const float4*)&A[(size_t)(bm + ar + 64) * lda + k0 + ac];
#pragma unroll
        for (int i = 0; i < BLD; ++i)
            bv[i] = *(const float4*)&B[(size_t)(k0 + brw + 8 * i) * ldb + bn + bcl];
    };
    auto store_smem = [&](int buf) {
        uint4 u0 = make_uint4(f2tf32(av[0].x), f2tf32(av[0].y), f2tf32(av[0].z), f2tf32(av[0].w));
        uint4 u1 = make_uint4(f2tf32(av[1].x), f2tf32(av[1].y), f2tf32(av[1].z), f2tf32(av[1].w));
        *(uint4*)&As[buf][ar * AST + ac] = u0;
        *(uint4*)&As[buf][(ar + 64) * AST + ac] = u1;
#pragma unroll
        for (int i = 0; i < BLD; ++i) {
            uint4 ub = make_uint4(f2tf32(bv[i].x), f2tf32(bv[i].y), f2tf32(bv[i].z), f2tf32(bv[i].w));
            *(uint4*)&Bs[buf][(brw + 8 * i) * BST + bcl] = ub;
        }
    };

    float acc[MF][NF][4];
#pragma unroll
    for (int i = 0; i < MF; ++i)
#pragma unroll
        for (int j = 0; j < NF; ++j)
#pragma unroll
            for (int r = 0; r < 4; ++r) acc[i][j][r] = 0.0f;

    const int nk = K >> 4;
    load_regs(0);
    store_smem(0);
    __syncthreads();
    int buf = 0;

    for (int kt = 0; kt < nk; ++kt) {
        if (kt + 1 < nk) load_regs(kt + 1);
#pragma unroll
        for (int ks = 0; ks < 2; ++ks) {
            const int k = ks * 8;
            uint32_t af[MF][4], bf[NF][2];
#pragma unroll
            for (int mf = 0; mf < MF; ++mf) {
                int m = wr * WM + mf * 16 + lr;
                af[mf][0] = As[buf][m * AST + k + lc];
                af[mf][1] = As[buf][(m + 8) * AST + k + lc];
                af[mf][2] = As[buf][m * AST + k + lc + 4];
                af[mf][3] = As[buf][(m + 8) * AST + k + lc + 4];
            }
#pragma unroll
            for (int nf = 0; nf < NF; ++nf) {
                int n = wc * WN + nf * 8 + lr;
                bf[nf][0] = Bs[buf][(k + lc) * BST + n];
                bf[nf][1] = Bs[buf][(k + 4 + lc) * BST + n];
            }
#pragma unroll
            for (int mf = 0; mf < MF; ++mf)
#pragma unroll
                for (int nf = 0; nf < NF; ++nf)
                    mma_tf32(acc[mf][nf], af[mf], bf[nf]);
        }
        if (kt + 1 < nk) {
            store_smem(buf ^ 1);
            __syncthreads();
            buf ^= 1;
        }
    }

    // epilogue
#pragma unroll
    for (int mf = 0; mf < MF; ++mf) {
#pragma unroll
        for (int nf = 0; nf < NF; ++nf) {
            int row = bm + wr * WM + mf * 16 + lr;
            int col = bn + wc * WN + nf * 8 + lc * 2;
            float b0 = 0.0f, b1 = 0.0f;
            if (bias) { b0 = bias[col]; b1 = bias[col + 1]; }
            *(float2*)&C[(size_t)row * ldc + col] =
                make_float2(acc[mf][nf][0] + b0, acc[mf][nf][1] + b1);
            *(float2*)&C[(size_t)(row + 8) * ldc + col] =
                make_float2(acc[mf][nf][2] + b0, acc[mf][nf][3] + b1);
        }
    }
}

// ======================= scores: P = gate * Q @ K^T (tf32) =======================
// Block 128x128, K=64 entirely in smem. Both tiles stored [row][d], stride 68.
__global__ __launch_bounds__(256)
void scores_nt_tf32(const float* __restrict__ Q, const float* __restrict__ Kt,
                    float* __restrict__ P)
{
    extern __shared__ uint32_t sm[];
    uint32_t* As = sm;              // [128][68] queries
    uint32_t* Bs = sm + 128 * 68;   // [128][68] keys

    const int tid = threadIdx.x;
    const int lane = tid & 31, warp = tid >> 5;
    const int wr = warp & 1, wc = warp >> 1;    // 2 x 4 warp grid
    const int lr = lane >> 2, lc = lane & 3;
    const int bh = blockIdx.z, b = bh >> 4, h = bh & 15;
    const int mi = blockIdx.y * 128, nj = blockIdx.x * 128;

    const float* Ag = Q + (size_t)b * SS * EE + h * 64;
    const float* Bg = Kt + (size_t)b * SS * EE + h * 64;

#pragma unroll
    for (int it = 0; it < 8; ++it) {
        int idx = it * 1024 + tid * 4;
        int r = idx >> 6, k = idx & 63;
        float4 qa = *(const float4*)&Ag[(size_t)(mi + r) * EE + k];
        float4 ka = *(const float4*)&Bg[(size_t)(nj + r) * EE + k];
        *(uint4*)&As[r * 68 + k] = make_uint4(f2tf32(qa.x), f2tf32(qa.y), f2tf32(qa.z), f2tf32(qa.w));
        *(uint4*)&Bs[r * 68 + k] = make_uint4(f2tf32(ka.x), f2tf32(ka.y), f2tf32(ka.z), f2tf32(ka.w));
    }
    __syncthreads();

    float acc[4][4][4];
#pragma unroll
    for (int i = 0; i < 4; ++i)
#pragma unroll
        for (int j = 0; j < 4; ++j)
#pragma unroll
            for (int r = 0; r < 4; ++r) acc[i][j][r] = 0.0f;

#pragma unroll
    for (int ks = 0; ks < 8; ++ks) {
        const int k = ks * 8;
        uint32_t af[4][4], bf[4][2];
#pragma unroll
        for (int mf = 0; mf < 4; ++mf) {
            int m = wr * 64 + mf * 16 + lr;
            af[mf][0] = As[m * 68 + k + lc];
            af[mf][1] = As[(m + 8) * 68 + k + lc];
            af[mf][2] = As[m * 68 + k + lc + 4];
            af[mf][3] = As[(m + 8) * 68 + k + lc + 4];
        }
#pragma unroll
        for (int nf = 0; nf < 4; ++nf) {
            int n = wc * 32 + nf * 8 + lr;
            bf[nf][0] = Bs[n * 68 + k + lc];      // B^T(k, n) = Ksm[n][k]
            bf[nf][1] = Bs[n * 68 + k + lc + 4];
        }
#pragma unroll
        for (int mf = 0; mf < 4; ++mf)
#pragma unroll
            for (int nf = 0; nf < 4; ++nf)
                mma_tf32(acc[mf][nf], af[mf], bf[nf]);
    }

    const float g = g_gate[bh];
    float* Cbase = P + ((size_t)bh * SS + mi) * SS + nj;
#pragma unroll
    for (int mf = 0; mf < 4; ++mf) {
#pragma unroll
        for (int nf = 0; nf < 4; ++nf) {
            int row = wr * 64 + mf * 16 + lr;
            int col = wc * 32 + nf * 8 + lc * 2;
            *(float2*)&Cbase[(size_t)row * SS + col] =
                make_float2(acc[mf][nf][0] * g, acc[mf][nf][1] * g);
            *(float2*)&Cbase[(size_t)(row + 8) * SS + col] =
                make_float2(acc[mf][nf][2] * g, acc[mf][nf][3] * g);
        }
    }
}

// ---------------- softmax over j for all 16 heads + head-mean ---------------
__global__ __launch_bounds__(256)
void softmax_mean(float* __restrict__ Pm, float* __restrict__ om)
{
    __shared__ float meanbuf[SS];
    __shared__ float red[8];
    const int i = blockIdx.x, b = blockIdx.y;
    const int tid = threadIdx.x;
    const int lane = tid & 31, wid = tid >> 5;

#pragma unroll
    for (int r = 0; r < 8; ++r) meanbuf[tid + 256 * r] = 0.0f;

    for (int h = 0; h < HH; ++h) {
        float* row = Pm + ((size_t)(b * HH + h) * SS + i) * SS;
        float s[8];
        float mx = -3.4e38f;
#pragma unroll
        for (int r = 0; r < 8; ++r) { s[r] = row[tid + 256 * r]; mx = fmaxf(mx, s[r]); }
#pragma unroll
        for (int o = 16; o > 0; o >>= 1) mx = fmaxf(mx, __shfl_xor_sync(0xffffffffu, mx, o));
        if (lane == 0) red[wid] = mx;
        __syncthreads();
        float m2 = red[0];
#pragma unroll
        for (int w = 1; w < 8; ++w) m2 = fmaxf(m2, red[w]);
        __syncthreads();

        float sum = 0.0f;
#pragma unroll
        for (int r = 0; r < 8; ++r) { s[r] = fast_exp(s[r] - m2); sum += s[r]; }
#pragma unroll
        for (int o = 16; o > 0; o >>= 1) sum += __shfl_xor_sync(0xffffffffu, sum, o);
        if (lane == 0) red[wid] = sum;
        __syncthreads();
        float tot = 0.0f;
#pragma unroll
        for (int w = 0; w < 8; ++w) tot += red[w];
        float inv = 1.0f / tot;
#pragma unroll
        for (int r = 0; r < 8; ++r) {
            float p = s[r] * inv;
            row[tid + 256 * r] = p;
            meanbuf[tid + 256 * r] += p * 0.0625f;
        }
        __syncthreads();
    }
    float* o = om + (size_t)(b * SS + i) * SS;
#pragma unroll
    for (int r = 0; r < 8; ++r) o[tid + 256 * r] = meanbuf[tid + 256 * r];
}

// ---------------- launch ----------------
extern "C" void kernel_launch(void* const* d_in, const int* in_sizes, int n_in,
                              void* d_out, int out_size)
{
    const float* x   = (const float*)d_in[0];
    const float* sf  = (const float*)d_in[1];
    const float* Wq  = (const float*)d_in[2];
    const float* bq  = (const float*)d_in[3];
    const float* Wk  = (const float*)d_in[4];
    const float* bk  = (const float*)d_in[5];
    const float* Wv  = (const float*)d_in[6];
    const float* bv  = (const float*)d_in[7];
    const float* Ws1 = (const float*)d_in[8];
    const float* bs1 = (const float*)d_in[9];
    const float* Ws2 = (const float*)d_in[10];
    const float* bs2 = (const float*)d_in[11];
    const float* Wo  = (const float*)d_in[12];
    const float* bo  = (const float*)d_in[13];
    float* out = (float*)d_out;

    float *pQ, *pK, *pV, *pC, *pP;
    cudaGetSymbolAddress((void**)&pQ, g_Q);
    cudaGetSymbolAddress((void**)&pK, g_K);
    cudaGetSymbolAddress((void**)&pV, g_V);
    cudaGetSymbolAddress((void**)&pC, g_CTX);
    cudaGetSymbolAddress((void**)&pP, g_P);

    // 1. sync gate (tiny)
    gate_kernel<<<1, 256>>>(sf, Ws1, bs1, Ws2, bs2);

    // 2. QKV projections: [4096,1024] x [1024,1024], tf32 MMA
    dim3 gqkv(EE / 128, (BB * SS) / 128, 1);
    gemm_nn_tf32<128, 2, 4><<<gqkv, 256>>>(x, Wq, bq, pQ, EE, EE, EE, EE, 0, 0, 0, 0, 0, 0);
    gemm_nn_tf32<128, 2, 4><<<gqkv, 256>>>(x, Wk, bk, pK, EE, EE, EE, EE, 0, 0, 0, 0, 0, 0);
    gemm_nn_tf32<128, 2, 4><<<gqkv, 256>>>(x, Wv, bv, pV, EE, EE, EE, EE, 0, 0, 0, 0, 0, 0);

    // 3. scores = gate/sqrt(DH) * Q K^T  (per b,h), tf32 MMA
    cudaFuncSetAttribute(scores_nt_tf32, cudaFuncAttributeMaxDynamicSharedMemorySize,
                         2 * 128 * 68 * 4);
    scores_nt_tf32<<<dim3(SS / 128, SS / 128, BB * HH), 256, 2 * 128 * 68 * 4>>>(pQ, pK, pP);

    // 4. softmax (in-place) + head-mean -> second half of d_out
    softmax_mean<<<dim3(SS, BB), 256>>>(pP, out + (size_t)BB * SS * EE);

    // 5. ctx = P @ V (per b,h), tf32 MMA; N=64
    gemm_nn_tf32<64, 4, 2><<<dim3(1, SS / 128, BB * HH), 256>>>(
        pP, pV, nullptr, pC, SS, SS, EE, EE,
        (size_t)HH * SS * SS, (size_t)SS * SS,      // A strides (b, h)
        (size_t)SS * EE, 64,                        // B strides
        (size_t)SS * EE, 64);                       // C strides

    // 6. out = ctx @ Wo + bo -> first half of d_out
    gemm_nn_tf32<128, 2, 4><<<dim3(EE / 128, (BB * SS) / 128, 1), 256>>>(
        pC, Wo, bo, out, EE, EE, EE, EE, 0, 0, 0, 0, 0, 0);

    (void)in_sizes; (void)n_in; (void)out_size;
}

// round 3
// speedup vs baseline: 1.9469x; 1.0003x over previous
#include <cuda_runtime.h>
#include <cstdint>
#include <cstddef>

#define BB 2
#define SS 2048
#define EE 1024
#define HH 16
#define DHD 64
#define HID 256

// ---------------- scratch (device globals: allocation-free) ----------------
__device__ float g_Q[(size_t)BB * SS * EE];
__device__ float g_K[(size_t)BB * SS * EE];
__device__ float g_V[(size_t)BB * SS * EE];
__device__ float g_CTX[(size_t)BB * SS * EE];
__device__ float g_P[(size_t)BB * HH * SS * SS];   // 537 MB scores/probs
__device__ float g_gate[BB * HH];

// ---------------- helpers ----------------
__device__ __forceinline__ float fast_exp(float x) {
    float y = x * 1.4426950408889634f;
    float n = rintf(y);
    float t = (y - n) * 0.6931471805599453f;
    float p = 1.0f + t * (1.0f + t * (0.5f + t * (0.16666667f +
              t * (0.041666668f + t * 0.008333334f))));
    n = fmaxf(n, -126.0f);
    return p * __int_as_float(((int)n + 127) << 23);
}

__device__ __forceinline__ uint32_t f2tf32(float x) {
    uint32_t r; asm("cvt.rna.tf32.f32 %0, %1;" : "=r"(r) : "f"(x)); return r;
}

__device__ __forceinline__ void mma_tf32(float* d, const uint32_t* a, const uint32_t* b) {
    asm volatile("mma.sync.aligned.m16n8k8.row.col.f32.tf32.tf32.f32 "
                 "{%0,%1,%2,%3}, {%4,%5,%6,%7}, {%8,%9}, {%0,%1,%2,%3};"
                 : "+f"(d[0]), "+f"(d[1]), "+f"(d[2]), "+f"(d[3])
                 : "r"(a[0]), "r"(a[1]), "r"(a[2]), "r"(a[3]),
                   "r"(b[0]), "r"(b[1]));
}

__device__ __forceinline__ void ldsm_x4(uint32_t* r, uint32_t addr) {
    asm volatile("ldmatrix.sync.aligned.m8n8.x4.shared.b16 {%0,%1,%2,%3}, [%4];"
                 : "=r"(r[0]), "=r"(r[1]), "=r"(r[2]), "=r"(r[3]) : "r"(addr));
}

// ---------------- sync gate ----------------
__global__ void gate_kernel(const float* __restrict__ sf,
                            const float* __restrict__ Ws1, const float* __restrict__ bs1,
                            const float* __restrict__ Ws2, const float* __restrict__ bs2)
{
    __shared__ float h1[BB][HID];
    int t = threadIdx.x;
    for (int b = 0; b < BB; ++b) {
        float acc = bs1[t];
        for (int e = 0; e < EE; ++e)
            acc += sf[b * EE + e] * Ws1[(size_t)e * HID + t];
        h1[b][t] = fmaxf(acc, 0.0f);
    }
    __syncthreads();
    if (t < BB * HH) {
        int b = t / HH, h = t % HH;
        float acc = bs2[h];
        for (int k = 0; k < HID; ++k)
            acc += h1[b][k] * Ws2[k * HH + h];
        float sig = 1.0f / (1.0f + __expf(-acc));
        g_gate[b * HH + h] = sig * 0.125f;
    }
}

// ======================= generic NN tf32 GEMM (LDSM A-fragments) =============
template<int BN, int WR, int WC>
__global__ __launch_bounds__(256)
void gemm_nn_tf32(const float* __restrict__ A, const float* __restrict__ B,
                  const float* __restrict__ bias, float* __restrict__ C,
                  int K, int lda, int ldb, int ldc,
                  size_t sAb, size_t sAh, size_t sBb, size_t sBh,
                  size_t sCb, size_t sCh)
{
    constexpr int WM = 128 / WR;
    constexpr int WN = BN / WC;
    constexpr int MF = WM / 16;
    constexpr int NF = WN / 8;
    constexpr int AST = 20;
    constexpr int BST = BN + 8;
    constexpr int BLD = BN / 64;

    __shared__ uint32_t As[2][128 * AST];
    __shared__ uint32_t Bs[2][16 * BST];

    const int tid = threadIdx.x;
    const int lane = tid & 31, warp = tid >> 5;
    const int wr = warp % WR, wc = warp / WR;
    const int lr = lane >> 2, lc = lane & 3;

    const int z = blockIdx.z, zb = z >> 4, zh = z & 15;
    A += zb * sAb + zh * sAh;
    B += zb * sBb + zh * sBh;
    C += zb * sCb + zh * sCh;

    const int bm = blockIdx.y * 128;
    const int bn = blockIdx.x * BN;

    const int ar = tid >> 2, ac = (tid & 3) * 4;
    const int brw = (BLD == 2) ? (tid >> 5) : (tid >> 4);
    const int bcl = (BLD == 2) ? ((tid & 31) * 4) : ((tid & 15) * 4);

    // LDSM lane addressing for A fragments
    const int a_row_l = wr * WM + (lane & 15);
    const int a_csel = (lane >> 4) << 2;     // 0 or 4
    const uint32_t As_u32[2] = { (uint32_t)__cvta_generic_to_shared(&As[0][0]),
                                 (uint32_t)__cvta_generic_to_shared(&As[1][0]) };

    float4 av[2], bv[BLD];

    auto load_regs = [&](int kt) {
        int k0 = kt * 16;
        av[0] = *(const float4*)&A[(size_t)(bm + ar) * lda + k0 + ac];
        av[1] = *(const float4*)&A[(size_t)(bm + ar + 64) * lda + k0 + ac];
#pragma unroll
        for (int i = 0; i < BLD; ++i)
            bv[i] = *(const float4*)&B[(size_t)(k0 + brw + 8 * i) * ldb + bn + bcl];
    };
    auto store_smem = [&](int buf) {
        uint4 u0 = make_uint4(f2tf32(av[0].x), f2tf32(av[0].y), f2tf32(av[0].z), f2tf32(av[0].w));
        uint4 u1 = make_uint4(f2tf32(av[1].x), f2tf32(av[1].y), f2tf32(av[1].z), f2tf32(av[1].w));
        *(uint4*)&As[buf][ar * AST + ac] = u0;
        *(uint4*)&As[buf][(ar + 64) * AST + ac] = u1;
#pragma unroll
        for (int i = 0; i < BLD; ++i) {
            uint4 ub = make_uint4(f2tf32(bv[i].x), f2tf32(bv[i].y), f2tf32(bv[i].z), f2tf32(bv[i].w));
            *(uint4*)&Bs[buf][(brw + 8 * i) * BST + bcl] = ub;
        }
    };

    float acc[MF][NF][4];
#pragma unroll
    for (int i = 0; i < MF; ++i)
#pragma unroll
        for (int j = 0; j < NF; ++j)
#pragma unroll
            for (int r = 0; r < 4; ++r) acc[i][j][r] = 0.0f;

    const int nk = K >> 4;
    load_regs(0);
    store_smem(0);
    __syncthreads();
    int buf = 0;

    for (int kt = 0; kt < nk; ++kt) {
        if (kt + 1 < nk) load_regs(kt + 1);
#pragma unroll
        for (int ks = 0; ks < 2; ++ks) {
            const int k = ks * 8;
            uint32_t af[MF][4], bf[NF][2];
#pragma unroll
            for (int mf = 0; mf < MF; ++mf)
                ldsm_x4(af[mf], As_u32[buf] +
                        (uint32_t)(((a_row_l + mf * 16) * AST + k + a_csel) * 4));
#pragma unroll
            for (int nf = 0; nf < NF; ++nf) {
                int n = wc * WN + nf * 8 + lr;
                bf[nf][0] = Bs[buf][(k + lc) * BST + n];
                bf[nf][1] = Bs[buf][(k + 4 + lc) * BST + n];
            }
#pragma unroll
            for (int mf = 0; mf < MF; ++mf)
#pragma unroll
                for (int nf = 0; nf < NF; ++nf)
                    mma_tf32(acc[mf][nf], af[mf], bf[nf]);
        }
        if (kt + 1 < nk) {
            store_smem(buf ^ 1);
            __syncthreads();
            buf ^= 1;
        }
    }

    // epilogue
#pragma unroll
    for (int nf = 0; nf < NF; ++nf) {
        int col = bn + wc * WN + nf * 8 + lc * 2;
        float b0 = 0.0f, b1 = 0.0f;
        if (bias) { b0 = bias[col]; b1 = bias[col + 1]; }
#pragma unroll
        for (int mf = 0; mf < MF; ++mf) {
            int row = bm + wr * WM + mf * 16 + lr;
            *(float2*)&C[(size_t)row * ldc + col] =
                make_float2(acc[mf][nf][0] + b0, acc[mf][nf][1] + b1);
            *(float2*)&C[(size_t)(row + 8) * ldc + col] =
                make_float2(acc[mf][nf][2] + b0, acc[mf][nf][3] + b1);
        }
    }
}

// ======================= scores: P = gate * Q @ K^T (tf32, LDSM A+B) =========
__global__ __launch_bounds__(256)
void scores_nt_tf32(const float* __restrict__ Q, const float* __restrict__ Kt,
                    float* __restrict__ P)
{
    extern __shared__ uint32_t sm[];
    uint32_t* As = sm;              // [128][68] queries
    uint32_t* Bs = sm + 128 * 68;   // [128][68] keys

    const int tid = threadIdx.x;
    const int lane = tid & 31, warp = tid >> 5;
    const int wr = warp & 1, wc = warp >> 1;    // 2 x 4 warp grid
    const int lr = lane >> 2, lc = lane & 3;
    const int bh = blockIdx.z, b = bh >> 4, h = bh & 15;
    const int mi = blockIdx.y * 128, nj = blockIdx.x * 128;

    const float* Ag = Q + (size_t)b * SS * EE + h * 64;
    const float* Bg = Kt + (size_t)b * SS * EE + h * 64;

#pragma unroll
    for (int it = 0; it < 8; ++it) {
        int idx = it * 1024 + tid * 4;
        int r = idx >> 6, k = idx & 63;
        float4 qa = *(const float4*)&Ag[(size_t)(mi + r) * EE + k];
        float4 ka = *(const float4*)&Bg[(size_t)(nj + r) * EE + k];
        *(uint4*)&As[r * 68 + k] = make_uint4(f2tf32(qa.x), f2tf32(qa.y), f2tf32(qa.z), f2tf32(qa.w));
        *(uint4*)&Bs[r * 68 + k] = make_uint4(f2tf32(ka.x), f2tf32(ka.y), f2tf32(ka.z), f2tf32(ka.w));
    }
    __syncthreads();

    const uint32_t Abase = (uint32_t)__cvta_generic_to_shared(As);
    const uint32_t Bbase = (uint32_t)__cvta_generic_to_shared(Bs);
    // A LDSM lanes: rows (lane&15), col select by lane>>4
    const int a_row_l = wr * 64 + (lane & 15);
    const int a_csel = (lane >> 4) << 2;
    // B LDSM x4 packs two n-fragments: lanes 0-7 rows n0..7 @k, 8-15 same rows @k+4,
    // 16-23 rows n0+8..15 @k, 24-31 @k+4
    const int b_row_l = wc * 32 + (lane & 7) + ((lane >> 4) << 3);
    const int b_csel = (lane & 8) ? 4 : 0;

    float acc[4][4][4];
#pragma unroll
    for (int i = 0; i < 4; ++i)
#pragma unroll
        for (int j = 0; j < 4; ++j)
#pragma unroll
            for (int r = 0; r < 4; ++r) acc[i][j][r] = 0.0f;

#pragma unroll
    for (int ks = 0; ks < 8; ++ks) {
        const int k = ks * 8;
        uint32_t af[4][4], bf[4][2];
#pragma unroll
        for (int mf = 0; mf < 4; ++mf)
            ldsm_x4(af[mf], Abase + (uint32_t)(((a_row_l + mf * 16) * 68 + k + a_csel) * 4));
#pragma unroll
        for (int np = 0; np < 2; ++np) {
            uint32_t r4[4];
            ldsm_x4(r4, Bbase + (uint32_t)(((b_row_l + np * 16) * 68 + k + b_csel) * 4));
            bf[np * 2][0] = r4[0]; bf[np * 2][1] = r4[1];
            bf[np * 2 + 1][0] = r4[2]; bf[np * 2 + 1][1] = r4[3];
        }
#pragma unroll
        for (int mf = 0; mf < 4; ++mf)
#pragma unroll
            for (int nf = 0; nf < 4; ++nf)
                mma_tf32(acc[mf][nf], af[mf], bf[nf]);
    }

    const float g = g_gate[bh];
    float* Cbase = P + ((size_t)bh * SS + mi) * SS + nj;
#pragma unroll
    for (int mf = 0; mf < 4; ++mf) {
#pragma unroll
        for (int nf = 0; nf < 4; ++nf) {
            int row = wr * 64 + mf * 16 + lr;
            int col = wc * 32 + nf * 8 + lc * 2;
            *(float2*)&Cbase[(size_t)row * SS + col] =
                make_float2(acc[mf][nf][0] * g, acc[mf][nf][1] * g);
            *(float2*)&Cbase[(size_t)(row + 8) * SS + col] =
                make_float2(acc[mf][nf][2] * g, acc[mf][nf][3] * g);
        }
    }
}

// ---------------- softmax over j for all 16 heads + head-mean ---------------
__global__ __launch_bounds__(256)
void softmax_mean(float* __restrict__ Pm, float* __restrict__ om)
{
    __shared__ float meanbuf[SS];
    __shared__ float red[8];
    const int i = blockIdx.x, b = blockIdx.y;
    const int tid = threadIdx.x;
    const int lane = tid & 31, wid = tid >> 5;

#pragma unroll
    for (int r = 0; r < 8; ++r) meanbuf[tid + 256 * r] = 0.0f;

    for (int h = 0; h < HH; ++h) {
        float* row = Pm + ((size_t)(b * HH + h) * SS + i) * SS;
        float s[8];
        float mx = -3.4e38f;
#pragma unroll
        for (int r = 0; r < 8; ++r) { s[r] = row[tid + 256 * r]; mx = fmaxf(mx, s[r]); }
#pragma unroll
        for (int o = 16; o > 0; o >>= 1) mx = fmaxf(mx, __shfl_xor_sync(0xffffffffu, mx, o));
        if (lane == 0) red[wid] = mx;
        __syncthreads();
        float m2 = red[0];
#pragma unroll
        for (int w = 1; w < 8; ++w) m2 = fmaxf(m2, red[w]);
        __syncthreads();

        float sum = 0.0f;
#pragma unroll
        for (int r = 0; r < 8; ++r) { s[r] = fast_exp(s[r] - m2); sum += s[r]; }
#pragma unroll
        for (int o = 16; o > 0; o >>= 1) sum += __shfl_xor_sync(0xffffffffu, sum, o);
        if (lane == 0) red[wid] = sum;
        __syncthreads();
        float tot = 0.0f;
#pragma unroll
        for (int w = 0; w < 8; ++w) tot += red[w];
        float inv = 1.0f / tot;
#pragma unroll
        for (int r = 0; r < 8; ++r) {
            float p = s[r] * inv;
            row[tid + 256 * r] = p;
            meanbuf[tid + 256 * r] += p * 0.0625f;
        }
        __syncthreads();
    }
    float* o = om + (size_t)(b * SS + i) * SS;
#pragma unroll
    for (int r = 0; r < 8; ++r) o[tid + 256 * r] = meanbuf[tid + 256 * r];
}

// ---------------- launch ----------------
extern "C" void kernel_launch(void* const* d_in, const int* in_sizes, int n_in,
                              void* d_out, int out_size)
{
    const float* x   = (const float*)d_in[0];
    const float* sf  = (const float*)d_in[1];
    const float* Wq  = (const float*)d_in[2];
    const float* bq  = (const float*)d_in[3];
    const float* Wk  = (const float*)d_in[4];
    const float* bk  = (const float*)d_in[5];
    const float* Wv  = (const float*)d_in[6];
    const float* bv  = (const float*)d_in[7];
    const float* Ws1 = (const float*)d_in[8];
    const float* bs1 = (const float*)d_in[9];
    const float* Ws2 = (const float*)d_in[10];
    const float* bs2 = (const float*)d_in[11];
    const float* Wo  = (const float*)d_in[12];
    const float* bo  = (const float*)d_in[13];
    float* out = (float*)d_out;

    float *pQ, *pK, *pV, *pC, *pP;
    cudaGetSymbolAddress((void**)&pQ, g_Q);
    cudaGetSymbolAddress((void**)&pK, g_K);
    cudaGetSymbolAddress((void**)&pV, g_V);
    cudaGetSymbolAddress((void**)&pC, g_CTX);
    cudaGetSymbolAddress((void**)&pP, g_P);

    // 1. sync gate (tiny)
    gate_kernel<<<1, 256>>>(sf, Ws1, bs1, Ws2, bs2);

    // 2. QKV projections: [4096,1024] x [1024,1024], tf32 MMA
    dim3 gqkv(EE / 128, (BB * SS) / 128, 1);
    gemm_nn_tf32<128, 2, 4><<<gqkv, 256>>>(x, Wq, bq, pQ, EE, EE, EE, EE, 0, 0, 0, 0, 0, 0);
    gemm_nn_tf32<128, 2, 4><<<gqkv, 256>>>(x, Wk, bk, pK, EE, EE, EE, EE, 0, 0, 0, 0, 0, 0);
    gemm_nn_tf32<128, 2, 4><<<gqkv, 256>>>(x, Wv, bv, pV, EE, EE, EE, EE, 0, 0, 0, 0, 0, 0);

    // 3. scores = gate/sqrt(DH) * Q K^T  (per b,h), tf32 MMA
    cudaFuncSetAttribute(scores_nt_tf32, cudaFuncAttributeMaxDynamicSharedMemorySize,
                         2 * 128 * 68 * 4);
    scores_nt_tf32<<<dim3(SS / 128, SS / 128, BB * HH), 256, 2 * 128 * 68 * 4>>>(pQ, pK, pP);

    // 4. softmax (in-place) + head-mean -> second half of d_out
    softmax_mean<<<dim3(SS, BB), 256>>>(pP, out + (size_t)BB * SS * EE);

    // 5. ctx = P @ V (per b,h), tf32 MMA; N=64
    gemm_nn_tf32<64, 4, 2><<<dim3(1, SS / 128, BB * HH), 256>>>(
        pP, pV, nullptr, pC, SS, SS, EE, EE,
        (size_t)HH * SS * SS, (size_t)SS * SS,
        (size_t)SS * EE, 64,
        (size_t)SS * EE, 64);

    // 6. out = ctx @ Wo + bo -> first half of d_out
    gemm_nn_tf32<128, 2, 4><<<dim3(EE / 128, (BB * SS) / 128, 1), 256>>>(
        pC, Wo, bo, out, EE, EE, EE, EE, 0, 0, 0, 0, 0, 0);

    (void)in_sizes; (void)n_in; (void)out_size;
}